// round 14
// baseline (speedup 1.0000x reference)
#include <cuda_runtime.h>
#include <cuda_fp16.h>
#include <cstdint>

#define T_TOK 4096
#define D_IN  2048
#define D_MOE 768
#define TWO_DM 1536

// ---- tiling (R7 proven config) ----
#define BM 128
#define BK 64                       // halves per K chunk = 128B swizzled row
#define A_BYTES  (BM * 128)         // 16 KB
#define B_BYTES  (128 * 128)        // 16 KB
#define STAGE_BYTES (A_BYTES + B_BYTES)
#define S_STAGES 3
#define SMEM_TOTAL (S_STAGES * STAGE_BYTES)   // 96 KB -> 2 CTAs/SM

#define G1_TILES (32 * 12)          // bid 0..383: bm-major (12 bn per bm)
#define G2_TILES (32 * 16)          // bid 384..895: bm-major (16 bn per bm)
#define N_TILES  (G1_TILES + G2_TILES)

// Scratch (device globals: allocation-free per harness rules)
__device__ __align__(16) __half g_xh[T_TOK * D_IN];
__device__ __align__(16) __half g_guw[TWO_DM * D_IN];
__device__ __align__(16) __half g_dw[D_IN * D_MOE];
__device__ __align__(16) __half g_h[T_TOK * D_MOE];
__device__ unsigned int g_ready[32];   // per 128-row block of h: finished G1 tiles (of 12)

// ---------------------------------------------------------------------------
// PTX helpers (non-'a' features only: cp.async, ldmatrix, mma.sync)
// ---------------------------------------------------------------------------
__device__ __forceinline__ uint32_t smem_u32(const void* p) {
    uint32_t a;
    asm("{ .reg .u64 t; cvta.to.shared.u64 t, %1; cvt.u32.u64 %0, t; }" : "=r"(a) : "l"(p));
    return a;
}
__device__ __forceinline__ void cp16(uint32_t saddr, const void* gaddr) {
    asm volatile("cp.async.cg.shared.global [%0], [%1], 16;" :: "r"(saddr), "l"(gaddr));
}
#define CP_COMMIT() asm volatile("cp.async.commit_group;" ::: "memory")
#define CP_WAIT(n)  asm volatile("cp.async.wait_group %0;" :: "n"(n) : "memory")

__device__ __forceinline__ void ldsm_x4(uint32_t& r0, uint32_t& r1, uint32_t& r2, uint32_t& r3,
                                        uint32_t addr) {
    asm volatile("ldmatrix.sync.aligned.m8n8.x4.shared.b16 {%0,%1,%2,%3}, [%4];"
                 : "=r"(r0), "=r"(r1), "=r"(r2), "=r"(r3) : "r"(addr));
}
__device__ __forceinline__ void mma_16816(float* c, const uint32_t* a, const uint32_t* b) {
    asm volatile(
        "mma.sync.aligned.m16n8k16.row.col.f32.f16.f16.f32 "
        "{%0,%1,%2,%3}, {%4,%5,%6,%7}, {%8,%9}, {%0,%1,%2,%3};"
        : "+f"(c[0]), "+f"(c[1]), "+f"(c[2]), "+f"(c[3])
        : "r"(a[0]), "r"(a[1]), "r"(a[2]), "r"(a[3]), "r"(b[0]), "r"(b[1]));
}
__device__ __forceinline__ void st_cs_f2(float* p, float a, float b) {
    asm volatile("st.global.cs.v2.f32 [%0], {%1, %2};" :: "l"(p), "f"(a), "f"(b) : "memory");
}
__device__ __forceinline__ float silu_f(float v) { return v / (1.0f + __expf(-v)); }

// ---------------------------------------------------------------------------
// fp32 -> fp16 conversion + ready-flag reset. expert_idx read on device.
// ---------------------------------------------------------------------------
__global__ void convert_kernel(const float* __restrict__ x,
                               const float* __restrict__ gup,
                               const float* __restrict__ dp,
                               const int* __restrict__ eidx) {
    if (blockIdx.x == 0 && threadIdx.x < 32) g_ready[threadIdx.x] = 0;
    const int e = *eidx;
    const float4* gu4 = (const float4*)(gup + (size_t)e * TWO_DM * D_IN);
    const float4* dw4 = (const float4*)(dp + (size_t)e * D_IN * D_MOE);
    const float4* x4 = (const float4*)x;
    uint4* xo = (uint4*)g_xh;
    uint4* go = (uint4*)g_guw;
    uint4* do_ = (uint4*)g_dw;
    const int stride = gridDim.x * blockDim.x;
    const int tid = blockIdx.x * blockDim.x + threadIdx.x;

    auto pack2 = [](float a, float b) {
        __half2 h = __floats2half2_rn(a, b);
        return *(uint32_t*)&h;
    };
    const int nx = T_TOK * D_IN / 8;
    for (int i = tid; i < nx; i += stride) {
        float4 v0 = x4[2 * i], v1 = x4[2 * i + 1];
        xo[i] = make_uint4(pack2(v0.x, v0.y), pack2(v0.z, v0.w),
                           pack2(v1.x, v1.y), pack2(v1.z, v1.w));
    }
    const int ng = TWO_DM * D_IN / 8;
    for (int i = tid; i < ng; i += stride) {
        float4 v0 = gu4[2 * i], v1 = gu4[2 * i + 1];
        go[i] = make_uint4(pack2(v0.x, v0.y), pack2(v0.z, v0.w),
                           pack2(v1.x, v1.y), pack2(v1.z, v1.w));
    }
    const int nd = D_IN * D_MOE / 8;
    for (int i = tid; i < nd; i += stride) {
        float4 v0 = dw4[2 * i], v1 = dw4[2 * i + 1];
        do_[i] = make_uint4(pack2(v0.x, v0.y), pack2(v0.z, v0.w),
                            pack2(v1.x, v1.y), pack2(v1.z, v1.w));
    }
}

// ---------------------------------------------------------------------------
// One GEMM tile (R7 body), fully templated, __noinline__ so ptxas allocates
// registers as max-over-paths instead of merging both bodies' pressure.
// ---------------------------------------------------------------------------
template <int KDIM, int NCHUNK, bool IS_G1>
__device__ __noinline__ void gemm_tile(int bm, int bn, uint32_t sbase,
                                       float* __restrict__ out) {
    const int tid = threadIdx.x, wid = tid >> 5, lane = tid & 31;
    const int wm = wid & 3, wn = wid >> 2;
    const int g = lane >> 2, q = lane & 3;

    const __half *Ap, *Bg, *Bu, *Bp;
    if (IS_G1) {
        Ap = g_xh + (size_t)bm * BM * KDIM;
        Bg = g_guw + (size_t)(bn * 64) * KDIM;
        Bu = g_guw + (size_t)(D_MOE + bn * 64) * KDIM;
        Bp = nullptr;
    } else {
        Ap = g_h + (size_t)bm * BM * KDIM;
        Bp = g_dw + (size_t)(bn * 128) * KDIM;
        Bg = Bu = nullptr;
    }

    auto load_stage = [&](int stage, int chunk) {
        const uint32_t sA = sbase + stage * STAGE_BYTES;
        const uint32_t sB = sA + A_BYTES;
        const int k0 = chunk * BK;
#pragma unroll
        for (int i = 0; i < 4; i++) {
            int gi = tid + i * 256;
            int r = gi >> 3, c = gi & 7;
            cp16(sA + r * 128 + ((c ^ (r & 7)) << 4), Ap + (size_t)r * KDIM + k0 + c * 8);
        }
#pragma unroll
        for (int i = 0; i < 4; i++) {
            int gi = tid + i * 256;
            int r = gi >> 3, c = gi & 7;
            const __half* src;
            if (IS_G1)
                src = (r < 64) ? (Bg + (size_t)r * KDIM) : (Bu + (size_t)(r - 64) * KDIM);
            else
                src = Bp + (size_t)r * KDIM;
            cp16(sB + r * 128 + ((c ^ (r & 7)) << 4), src + k0 + c * 8);
        }
        CP_COMMIT();
    };

    const int r7 = lane & 7;
    const int laneRowA = ((lane >> 3) & 1) * 8 + r7;
    const int kselA = lane >> 4;
    const int laneRowB = (lane >> 4) * 8 + r7;
    const int kselB = (lane >> 3) & 1;

    float acc[2][8][4];
#pragma unroll
    for (int a = 0; a < 2; a++)
#pragma unroll
        for (int b = 0; b < 8; b++)
#pragma unroll
            for (int c = 0; c < 4; c++) acc[a][b][c] = 0.f;

    load_stage(0, 0);
    load_stage(1, 1);

    for (int j = 0; j < NCHUNK; j++) {
        if (j == NCHUNK - 1) { CP_WAIT(0); } else { CP_WAIT(1); }
        __syncthreads();
        if (j + 2 < NCHUNK) load_stage((j + 2) % S_STAGES, j + 2);

        const uint32_t sA = sbase + (j % S_STAGES) * STAGE_BYTES;
        const uint32_t sB = sA + A_BYTES;

#pragma unroll
        for (int kk = 0; kk < 4; kk++) {
            uint32_t a[2][4];
#pragma unroll
            for (int mt = 0; mt < 2; mt++) {
                int row = wm * 32 + mt * 16 + laneRowA;
                uint32_t addr = sA + row * 128 + (((kk * 2 + kselA) ^ r7) << 4);
                ldsm_x4(a[mt][0], a[mt][1], a[mt][2], a[mt][3], addr);
            }
            uint32_t b[8][2];
#pragma unroll
            for (int p = 0; p < 4; p++) {
                int nbase;
                if (IS_G1) nbase = (p < 2) ? (wn * 32 + p * 16) : (64 + wn * 32 + (p - 2) * 16);
                else       nbase = wn * 64 + p * 16;
                int row = nbase + laneRowB;
                uint32_t addr = sB + row * 128 + (((kk * 2 + kselB) ^ r7) << 4);
                ldsm_x4(b[2 * p][0], b[2 * p][1], b[2 * p + 1][0], b[2 * p + 1][1], addr);
            }
#pragma unroll
            for (int mt = 0; mt < 2; mt++)
#pragma unroll
                for (int ni = 0; ni < 8; ni++)
                    mma_16816(acc[mt][ni], a[mt], b[ni]);
        }
    }

    if (IS_G1) {
#pragma unroll
        for (int mt = 0; mt < 2; mt++)
#pragma unroll
            for (int ni = 0; ni < 4; ni++) {
                int row = bm * BM + wm * 32 + mt * 16 + g;
                int col = bn * 64 + wn * 32 + ni * 8 + q * 2;
                float* cg = acc[mt][ni];
                float* cu = acc[mt][ni + 4];
                __half2 h01 = __floats2half2_rn(silu_f(cg[0]) * cu[0], silu_f(cg[1]) * cu[1]);
                __half2 h23 = __floats2half2_rn(silu_f(cg[2]) * cu[2], silu_f(cg[3]) * cu[3]);
                *(__half2*)&g_h[(size_t)row * D_MOE + col] = h01;
                *(__half2*)&g_h[(size_t)(row + 8) * D_MOE + col] = h23;
            }
        __threadfence();
        __syncthreads();
        if (threadIdx.x == 0) atomicAdd(&g_ready[bm], 1u);
    } else {
#pragma unroll
        for (int mt = 0; mt < 2; mt++)
#pragma unroll
            for (int ni = 0; ni < 8; ni++) {
                int row = bm * BM + wm * 32 + mt * 16 + g;
                int col = bn * 128 + wn * 64 + ni * 8 + q * 2;
                float* c = acc[mt][ni];
                st_cs_f2(&out[(size_t)row * D_IN + col], c[0], c[1]);
                st_cs_f2(&out[(size_t)(row + 8) * D_IN + col], c[2], c[3]);
            }
    }
}

// ---------------------------------------------------------------------------
// Single-launch fused GEMM: 896 CTAs. bid < 384 -> G1 tile (bm-major);
// else G2 tile, self-gated on g_ready[bm]. In-order block dispatch guarantees
// every G1 block is dispatched before any G2 block -> spin always terminates,
// and G2 blocks stream into slots as G1's tail retires (overlap in one node).
// ---------------------------------------------------------------------------
__global__ __launch_bounds__(256, 2) void moe_fused(float* __restrict__ out) {
    extern __shared__ char smem[];
    const uint32_t sbase = smem_u32(smem);
    const int bid = blockIdx.x;

    if (bid < G1_TILES) {
        gemm_tile<D_IN, D_IN / BK, true>(bid / 12, bid % 12, sbase, out);
    } else {
        const int i2 = bid - G1_TILES;
        const int bm = i2 / 16, bn = i2 % 16;
        if (threadIdx.x == 0) {
            while (atomicAdd(&g_ready[bm], 0u) < 12u) __nanosleep(64);
        }
        __syncthreads();
        __threadfence();   // acquire ordering for g_h reads
        gemm_tile<D_MOE, D_MOE / BK, false>(bm, bn, sbase, out);
    }
}

// ---------------------------------------------------------------------------
extern "C" void kernel_launch(void* const* d_in, const int* in_sizes, int n_in,
                              void* d_out, int out_size) {
    const float* x = (const float*)d_in[0];
    const float* gup = (const float*)d_in[1];
    const float* dp = (const float*)d_in[2];
    const int* eidx = (const int*)d_in[3];
    float* out = (float*)d_out;

    cudaFuncSetAttribute(moe_fused, cudaFuncAttributeMaxDynamicSharedMemorySize, SMEM_TOTAL);

    convert_kernel<<<2048, 256>>>(x, gup, dp, eidx);
    moe_fused<<<N_TILES, 256, SMEM_TOTAL>>>(out);
}

// round 15
// speedup vs baseline: 1.1718x; 1.1718x over previous
#include <cuda_runtime.h>
#include <cuda_fp16.h>
#include <cstdint>

#define T_TOK 4096
#define D_IN  2048
#define D_MOE 768
#define TWO_DM 1536

// ---- tiling (R7/R13 proven config) ----
#define BM 128
#define BK 64                       // halves per K chunk = 128B swizzled row
#define A_BYTES  (BM * 128)         // 16 KB
#define B_BYTES  (128 * 128)        // 16 KB
#define STAGE_BYTES (A_BYTES + B_BYTES)
#define S_STAGES 3
#define SMEM_TOTAL (S_STAGES * STAGE_BYTES)   // 96 KB -> 2 CTAs/SM

// Scratch (device globals: allocation-free per harness rules)
__device__ __align__(16) __half g_xh[T_TOK * D_IN];
__device__ __align__(16) __half g_guw[TWO_DM * D_IN];
__device__ __align__(16) __half g_dw[D_IN * D_MOE];
__device__ __align__(16) __half g_h[T_TOK * D_MOE];
__device__ unsigned int g_ready[32];   // per 128-row block of h: finished G1 tiles (of 12)

// ---------------------------------------------------------------------------
// PTX helpers (non-'a' features only: cp.async, ldmatrix, mma.sync, griddepcontrol)
// ---------------------------------------------------------------------------
__device__ __forceinline__ uint32_t smem_u32(const void* p) {
    uint32_t a;
    asm("{ .reg .u64 t; cvta.to.shared.u64 t, %1; cvt.u32.u64 %0, t; }" : "=r"(a) : "l"(p));
    return a;
}
__device__ __forceinline__ void cp16(uint32_t saddr, const void* gaddr) {
    asm volatile("cp.async.cg.shared.global [%0], [%1], 16;" :: "r"(saddr), "l"(gaddr));
}
#define CP_COMMIT() asm volatile("cp.async.commit_group;" ::: "memory")
#define CP_WAIT(n)  asm volatile("cp.async.wait_group %0;" :: "n"(n) : "memory")

__device__ __forceinline__ void ldsm_x4(uint32_t& r0, uint32_t& r1, uint32_t& r2, uint32_t& r3,
                                        uint32_t addr) {
    asm volatile("ldmatrix.sync.aligned.m8n8.x4.shared.b16 {%0,%1,%2,%3}, [%4];"
                 : "=r"(r0), "=r"(r1), "=r"(r2), "=r"(r3) : "r"(addr));
}
__device__ __forceinline__ void mma_16816(float* c, const uint32_t* a, const uint32_t* b) {
    asm volatile(
        "mma.sync.aligned.m16n8k16.row.col.f32.f16.f16.f32 "
        "{%0,%1,%2,%3}, {%4,%5,%6,%7}, {%8,%9}, {%0,%1,%2,%3};"
        : "+f"(c[0]), "+f"(c[1]), "+f"(c[2]), "+f"(c[3])
        : "r"(a[0]), "r"(a[1]), "r"(a[2]), "r"(a[3]), "r"(b[0]), "r"(b[1]));
}
__device__ __forceinline__ void st_cs_f2(float* p, float a, float b) {
    asm volatile("st.global.cs.v2.f32 [%0], {%1, %2};" :: "l"(p), "f"(a), "f"(b) : "memory");
}
__device__ __forceinline__ float silu_f(float v) { return v / (1.0f + __expf(-v)); }

// ---------------------------------------------------------------------------
// fp32 -> fp16 conversion + ready-flag reset. expert_idx read on device.
// ---------------------------------------------------------------------------
__global__ void convert_kernel(const float* __restrict__ x,
                               const float* __restrict__ gup,
                               const float* __restrict__ dp,
                               const int* __restrict__ eidx) {
    if (blockIdx.x == 0 && threadIdx.x < 32) g_ready[threadIdx.x] = 0;
    const int e = *eidx;
    const float4* gu4 = (const float4*)(gup + (size_t)e * TWO_DM * D_IN);
    const float4* dw4 = (const float4*)(dp + (size_t)e * D_IN * D_MOE);
    const float4* x4 = (const float4*)x;
    uint4* xo = (uint4*)g_xh;
    uint4* go = (uint4*)g_guw;
    uint4* do_ = (uint4*)g_dw;
    const int stride = gridDim.x * blockDim.x;
    const int tid = blockIdx.x * blockDim.x + threadIdx.x;

    auto pack2 = [](float a, float b) {
        __half2 h = __floats2half2_rn(a, b);
        return *(uint32_t*)&h;
    };
    const int nx = T_TOK * D_IN / 8;
    for (int i = tid; i < nx; i += stride) {
        float4 v0 = x4[2 * i], v1 = x4[2 * i + 1];
        xo[i] = make_uint4(pack2(v0.x, v0.y), pack2(v0.z, v0.w),
                           pack2(v1.x, v1.y), pack2(v1.z, v1.w));
    }
    const int ng = TWO_DM * D_IN / 8;
    for (int i = tid; i < ng; i += stride) {
        float4 v0 = gu4[2 * i], v1 = gu4[2 * i + 1];
        go[i] = make_uint4(pack2(v0.x, v0.y), pack2(v0.z, v0.w),
                           pack2(v1.x, v1.y), pack2(v1.z, v1.w));
    }
    const int nd = D_IN * D_MOE / 8;
    for (int i = tid; i < nd; i += stride) {
        float4 v0 = dw4[2 * i], v1 = dw4[2 * i + 1];
        do_[i] = make_uint4(pack2(v0.x, v0.y), pack2(v0.z, v0.w),
                            pack2(v1.x, v1.y), pack2(v1.z, v1.w));
    }
}

// ---------------------------------------------------------------------------
// Pipelined HMMA GEMM, 2 CTAs/SM, 256 threads = 8 warps (4M x 2N). R13 bodies.
// G1: triggers dependent launch at entry (PDL); publishes g_ready[bm] per tile.
// G2: PDL-launched, CTAs self-gate on g_ready[bm]==12 and fill G1's tail.
// ---------------------------------------------------------------------------
template <int KDIM, int NCHUNK, bool IS_G1>
__global__ __launch_bounds__(256, 2) void gemm_hmma(float* __restrict__ out) {
    extern __shared__ char smem[];
    const uint32_t sbase = smem_u32(smem);
    const int tid = threadIdx.x, wid = tid >> 5, lane = tid & 31;
    const int wm = wid & 3, wn = wid >> 2;
    const int g = lane >> 2, q = lane & 3;
    const int bn = blockIdx.x, bm = blockIdx.y;

    if (IS_G1) {
        // allow the dependent grid (G2) to start dispatching once all G1 CTAs
        // have launched; correctness is carried by the g_ready protocol.
        asm volatile("griddepcontrol.launch_dependents;");
    } else {
        // wait until this 128-row block of h is fully produced by G1
        if (tid == 0) {
            while (atomicAdd(&g_ready[bm], 0u) < 12u) __nanosleep(64);
        }
        __syncthreads();
        __threadfence();   // acquire ordering for g_h reads below
    }

    const __half *Ap, *Bg, *Bu, *Bp;
    if (IS_G1) {
        Ap = g_xh + (size_t)bm * BM * KDIM;
        Bg = g_guw + (size_t)(bn * 64) * KDIM;
        Bu = g_guw + (size_t)(D_MOE + bn * 64) * KDIM;
        Bp = nullptr;
    } else {
        Ap = g_h + (size_t)bm * BM * KDIM;
        Bp = g_dw + (size_t)(bn * 128) * KDIM;
        Bg = Bu = nullptr;
    }

    auto load_stage = [&](int stage, int chunk) {
        const uint32_t sA = sbase + stage * STAGE_BYTES;
        const uint32_t sB = sA + A_BYTES;
        const int k0 = chunk * BK;
#pragma unroll
        for (int i = 0; i < 4; i++) {
            int gi = tid + i * 256;
            int r = gi >> 3, c = gi & 7;
            cp16(sA + r * 128 + ((c ^ (r & 7)) << 4), Ap + (size_t)r * KDIM + k0 + c * 8);
        }
#pragma unroll
        for (int i = 0; i < 4; i++) {
            int gi = tid + i * 256;
            int r = gi >> 3, c = gi & 7;
            const __half* src;
            if (IS_G1)
                src = (r < 64) ? (Bg + (size_t)r * KDIM) : (Bu + (size_t)(r - 64) * KDIM);
            else
                src = Bp + (size_t)r * KDIM;
            cp16(sB + r * 128 + ((c ^ (r & 7)) << 4), src + k0 + c * 8);
        }
        CP_COMMIT();
    };

    const int r7 = lane & 7;
    const int laneRowA = ((lane >> 3) & 1) * 8 + r7;
    const int kselA = lane >> 4;
    const int laneRowB = (lane >> 4) * 8 + r7;
    const int kselB = (lane >> 3) & 1;

    float acc[2][8][4];
#pragma unroll
    for (int a = 0; a < 2; a++)
#pragma unroll
        for (int b = 0; b < 8; b++)
#pragma unroll
            for (int c = 0; c < 4; c++) acc[a][b][c] = 0.f;

    load_stage(0, 0);
    load_stage(1, 1);

    for (int j = 0; j < NCHUNK; j++) {
        if (j == NCHUNK - 1) { CP_WAIT(0); } else { CP_WAIT(1); }
        __syncthreads();
        if (j + 2 < NCHUNK) load_stage((j + 2) % S_STAGES, j + 2);

        const uint32_t sA = sbase + (j % S_STAGES) * STAGE_BYTES;
        const uint32_t sB = sA + A_BYTES;

#pragma unroll
        for (int kk = 0; kk < 4; kk++) {
            uint32_t a[2][4];
#pragma unroll
            for (int mt = 0; mt < 2; mt++) {
                int row = wm * 32 + mt * 16 + laneRowA;
                uint32_t addr = sA + row * 128 + (((kk * 2 + kselA) ^ r7) << 4);
                ldsm_x4(a[mt][0], a[mt][1], a[mt][2], a[mt][3], addr);
            }
            uint32_t b[8][2];
#pragma unroll
            for (int p = 0; p < 4; p++) {
                int nbase;
                if (IS_G1) nbase = (p < 2) ? (wn * 32 + p * 16) : (64 + wn * 32 + (p - 2) * 16);
                else       nbase = wn * 64 + p * 16;
                int row = nbase + laneRowB;
                uint32_t addr = sB + row * 128 + (((kk * 2 + kselB) ^ r7) << 4);
                ldsm_x4(b[2 * p][0], b[2 * p][1], b[2 * p + 1][0], b[2 * p + 1][1], addr);
            }
#pragma unroll
            for (int mt = 0; mt < 2; mt++)
#pragma unroll
                for (int ni = 0; ni < 8; ni++)
                    mma_16816(acc[mt][ni], a[mt], b[ni]);
        }
    }

    if (IS_G1) {
#pragma unroll
        for (int mt = 0; mt < 2; mt++)
#pragma unroll
            for (int ni = 0; ni < 4; ni++) {
                int row = bm * BM + wm * 32 + mt * 16 + g;
                int col = bn * 64 + wn * 32 + ni * 8 + q * 2;
                float* cg = acc[mt][ni];
                float* cu = acc[mt][ni + 4];
                __half2 h01 = __floats2half2_rn(silu_f(cg[0]) * cu[0], silu_f(cg[1]) * cu[1]);
                __half2 h23 = __floats2half2_rn(silu_f(cg[2]) * cu[2], silu_f(cg[3]) * cu[3]);
                *(__half2*)&g_h[(size_t)row * D_MOE + col] = h01;
                *(__half2*)&g_h[(size_t)(row + 8) * D_MOE + col] = h23;
            }
        // publish: this (bm, bn) h-tile is complete
        __threadfence();
        __syncthreads();
        if (tid == 0) atomicAdd(&g_ready[bm], 1u);
    } else {
#pragma unroll
        for (int mt = 0; mt < 2; mt++)
#pragma unroll
            for (int ni = 0; ni < 8; ni++) {
                int row = bm * BM + wm * 32 + mt * 16 + g;
                int col = bn * 128 + wn * 64 + ni * 8 + q * 2;
                float* c = acc[mt][ni];
                st_cs_f2(&out[(size_t)row * D_IN + col], c[0], c[1]);
                st_cs_f2(&out[(size_t)(row + 8) * D_IN + col], c[2], c[3]);
            }
    }
}

// ---------------------------------------------------------------------------
extern "C" void kernel_launch(void* const* d_in, const int* in_sizes, int n_in,
                              void* d_out, int out_size) {
    const float* x = (const float*)d_in[0];
    const float* gup = (const float*)d_in[1];
    const float* dp = (const float*)d_in[2];
    const int* eidx = (const int*)d_in[3];
    float* out = (float*)d_out;

    cudaFuncSetAttribute(gemm_hmma<D_IN, D_IN / BK, true>,
                         cudaFuncAttributeMaxDynamicSharedMemorySize, SMEM_TOTAL);
    cudaFuncSetAttribute(gemm_hmma<D_MOE, D_MOE / BK, false>,
                         cudaFuncAttributeMaxDynamicSharedMemorySize, SMEM_TOTAL);

    convert_kernel<<<2048, 256>>>(x, gup, dp, eidx);

    // G1: normal launch (full dependency on convert)
    gemm_hmma<D_IN, D_IN / BK, true><<<dim3(12, 32), 256, SMEM_TOTAL>>>(nullptr);

    // G2: programmatic dependent launch — may begin dispatching while G1 runs;
    // device-side g_ready gating enforces the h dependency per row-block.
    {
        cudaLaunchConfig_t cfg = {};
        cfg.gridDim = dim3(16, 32);
        cfg.blockDim = dim3(256);
        cfg.dynamicSmemBytes = SMEM_TOTAL;
        cfg.stream = 0;
        cudaLaunchAttribute attr[1];
        attr[0].id = cudaLaunchAttributeProgrammaticStreamSerialization;
        attr[0].val.programmaticStreamSerializationAllowed = 1;
        cfg.attrs = attr;
        cfg.numAttrs = 1;
        cudaLaunchKernelEx(&cfg, gemm_hmma<D_MOE, D_MOE / BK, false>, out);
    }
}